// round 4
// baseline (speedup 1.0000x reference)
#include <cuda_runtime.h>
#include <math.h>
#include <stdint.h>

#define B 4
#define C 64
#define CQK 128
#define HDIM 256
#define WDIM 256
#define HW 65536
#define HEADS 8

// ---------------- scratch ----------------------------------------------------
__device__ float g_qk_pre[(size_t)B * CQK * HW];
__device__ float g_y[(size_t)B * C * HW];
__device__ float g_sumsq[B * CQK];
__device__ float g_gram[B * HEADS * 8 * 8];
__device__ float g_M[B * C * C];
__device__ float g_Wt[25 * 64 * 64];

// ---------------- helpers -----------------------------------------------------
__device__ __forceinline__ float to_tf32(float v) {
    uint32_t u;
    asm("cvt.rna.tf32.f32 %0, %1;" : "=r"(u) : "f"(v));
    return __uint_as_float(u);
}

__device__ __forceinline__ void mma_tf32(float* d, const uint32_t* a, const uint32_t* b) {
    asm volatile(
        "mma.sync.aligned.m16n8k8.row.col.f32.tf32.tf32.f32 "
        "{%0,%1,%2,%3}, {%4,%5,%6,%7}, {%8,%9}, {%0,%1,%2,%3};"
        : "+f"(d[0]), "+f"(d[1]), "+f"(d[2]), "+f"(d[3])
        : "r"(a[0]), "r"(a[1]), "r"(a[2]), "r"(a[3]), "r"(b[0]), "r"(b[1]));
}

__device__ __forceinline__ void cp_async16(uint32_t daddr, const void* src) {
    asm volatile("cp.async.cg.shared.global [%0], [%1], 16;" :: "r"(daddr), "l"(src));
}

// ---------------- K_zero ------------------------------------------------------
__global__ void k_zero() {
    int i = blockIdx.x * blockDim.x + threadIdx.x;
    if (i < B * CQK) g_sumsq[i] = 0.0f;
    if (i < B * HEADS * 64) g_gram[i] = 0.0f;
}

// ---------------- K_wt --------------------------------------------------------
__global__ void k_wt(const float* __restrict__ w_m2) {
    int i = blockIdx.x * 256 + threadIdx.x;
    if (i < 25 * 4096) {
        int t = i / 4096;
        int rem = i & 4095;
        int ic = rem >> 6, oc = rem & 63;
        g_Wt[i] = to_tf32(w_m2[(oc * 64 + ic) * 25 + t]);
    }
}

// ---------------- K0: tf32-MMA fused 1x1 convs --------------------------------
// 128 threads (4 warps), M=128 px (2 frags/warp), N=192 split 2x96, K=64.
#define PSTR 136
#define OSTR 200

__global__ __launch_bounds__(128)
void k_pointwise(const float* __restrict__ x,
                 const float* __restrict__ w_qkv,
                 const float* __restrict__ b_qkv,
                 const float* __restrict__ w_m1,
                 const float* __restrict__ bn_g,
                 const float* __restrict__ bn_b,
                 const float* __restrict__ bn_m,
                 const float* __restrict__ bn_v) {
    extern __shared__ float sm[];
    float* xs     = sm;                  // 64 * 136
    float* ws     = xs + 64 * PSTR;      // 64 * 200
    float* sscale = ws + 64 * OSTR;      // 192
    float* sshift = sscale + 192;        // 192

    const int tid = threadIdx.x;
    const int b = blockIdx.y;
    const int p0 = blockIdx.x * 128;

    for (int i = tid; i < 128 * 64; i += 128) {
        int oc = i >> 6, ic = i & 63;
        ws[ic * OSTR + oc] = to_tf32(w_qkv[i]);
    }
    for (int i = tid; i < 64 * 64; i += 128) {
        int oc = i >> 6, ic = i & 63;
        ws[ic * OSTR + 128 + oc] = to_tf32(w_m1[i]);
    }
    for (int i = tid; i < 192; i += 128) {
        if (i < 128) { sscale[i] = 1.0f; sshift[i] = b_qkv[i]; }
        else {
            int cc = i - 128;
            float s = bn_g[cc] * rsqrtf(bn_v[cc] + 1e-5f);
            sscale[i] = s;
            sshift[i] = bn_b[cc] - bn_m[cc] * s;
        }
    }
    for (int i = tid * 4; i < 64 * 128; i += 512) {
        int ic = i >> 7, px = i & 127;
        float4 v = *(const float4*)(x + (size_t)(b * 64 + ic) * HW + p0 + px);
        float* d = xs + ic * PSTR + px;
        d[0] = to_tf32(v.x); d[1] = to_tf32(v.y);
        d[2] = to_tf32(v.z); d[3] = to_tf32(v.w);
    }
    __syncthreads();

    const int w = tid >> 5, lane = tid & 31;
    const int g = lane >> 2, t4 = lane & 3;
    const uint32_t* xsu = (const uint32_t*)xs;
    const uint32_t* wsu = (const uint32_t*)ws;

    for (int half = 0; half < 2; half++) {
        float acc[2][12][4];
#pragma unroll
        for (int m = 0; m < 2; m++)
#pragma unroll
            for (int n = 0; n < 12; n++)
#pragma unroll
                for (int j = 0; j < 4; j++) acc[m][n][j] = 0.0f;

#pragma unroll
        for (int ks = 0; ks < 8; ks++) {
            int ic = ks * 8 + t4;
            int m0 = w * 32 + g;
            uint32_t a0[4], a1[4];
            a0[0] = xsu[ic * PSTR + m0];
            a0[1] = xsu[ic * PSTR + m0 + 8];
            a0[2] = xsu[(ic + 4) * PSTR + m0];
            a0[3] = xsu[(ic + 4) * PSTR + m0 + 8];
            a1[0] = xsu[ic * PSTR + m0 + 16];
            a1[1] = xsu[ic * PSTR + m0 + 24];
            a1[2] = xsu[(ic + 4) * PSTR + m0 + 16];
            a1[3] = xsu[(ic + 4) * PSTR + m0 + 24];
            int bb0 = ic * OSTR + half * 96 + g;
#pragma unroll
            for (int n = 0; n < 12; n++) {
                uint32_t bb[2];
                bb[0] = wsu[bb0 + n * 8];
                bb[1] = wsu[bb0 + 4 * OSTR + n * 8];
                mma_tf32(acc[0][n], a0, bb);
                mma_tf32(acc[1][n], a1, bb);
            }
        }

#pragma unroll
        for (int m = 0; m < 2; m++) {
#pragma unroll
            for (int n = 0; n < 12; n++) {
#pragma unroll
                for (int j = 0; j < 4; j++) {
                    int oc = half * 96 + n * 8 + t4 * 2 + (j & 1);
                    int px = p0 + w * 32 + m * 16 + g + ((j >> 1) << 3);
                    float v = acc[m][n][j] * sscale[oc] + sshift[oc];
                    if (oc < 128)
                        g_qk_pre[(size_t)(b * 128 + oc) * HW + px] = v;
                    else
                        g_y[(size_t)(b * 64 + oc - 128) * HW + px] = to_tf32(v);
                }
            }
        }
    }
}

// ---------------- K1: fused depthwise3x3 + gram + sumsq (vectorized) ----------
// grid (8, 8, B*HEADS), 256 threads. Tile 32x32, 16 channels (8 q + 8 k).
// Thread (py = tid>>3, q = tid&7) computes outputs (py, 4q..4q+3).
#define RST 36
#define CST (34 * RST)   // 1224

__global__ __launch_bounds__(256)
void k_dwgram(const float* __restrict__ w_dw,
              const float* __restrict__ b_dw) {
    extern __shared__ float sm[];          // 16 * 1224 halo tiles
    float* wsm = sm + 16 * CST;            // 144
    float* bsm = wsm + 144;                // 16

    const int bh = blockIdx.z;
    const int b = bh >> 3, h = bh & 7;
    const int tx0 = blockIdx.x * 32, ty0 = blockIdx.y * 32;
    const int tid = threadIdx.x;

    for (int i = tid; i < 144; i += 256) {
        int c16 = i / 9, t = i - c16 * 9;
        int ch = (c16 < 8) ? h * 8 + c16 : 64 + h * 8 + (c16 - 8);
        wsm[i] = w_dw[ch * 9 + t];
    }
    if (tid < 16) {
        int ch = (tid < 8) ? h * 8 + tid : 64 + h * 8 + (tid - 8);
        bsm[tid] = b_dw[ch];
    }
    for (int i = tid; i < 16 * 1156; i += 256) {
        int c16 = i / 1156;
        int rem = i - c16 * 1156;
        int r = rem / 34, cc = rem - r * 34;
        int gy = ty0 - 1 + r, gx = tx0 - 1 + cc;
        int ch = (c16 < 8) ? h * 8 + c16 : 64 + h * 8 + (c16 - 8);
        float v = 0.0f;
        if (gy >= 0 && gy < HDIM && gx >= 0 && gx < WDIM)
            v = g_qk_pre[((size_t)b * CQK + ch) * HW + gy * WDIM + gx];
        sm[c16 * CST + r * RST + cc] = v;
    }
    __syncthreads();

    const int q = tid & 7, py = tid >> 3;
    const int base0 = py * RST + 4 * q;   // storage col 4q == input col 4q-1

    float dvq[8][4], gacc[64], ssq[16];
#pragma unroll
    for (int i = 0; i < 64; i++) gacc[i] = 0.0f;
#pragma unroll
    for (int i = 0; i < 16; i++) ssq[i] = 0.0f;

#pragma unroll
    for (int c16 = 0; c16 < 16; c16++) {
        const float4* rp = (const float4*)(sm + c16 * CST + base0);
        float rr[3][6];
#pragma unroll
        for (int dy = 0; dy < 3; dy++) {
            float4 a = rp[dy * (RST / 4)];
            float4 bb = rp[dy * (RST / 4) + 1];
            rr[dy][0] = a.x; rr[dy][1] = a.y; rr[dy][2] = a.z;
            rr[dy][3] = a.w; rr[dy][4] = bb.x; rr[dy][5] = bb.y;
        }
        float o[4];
        float bias = bsm[c16];
#pragma unroll
        for (int xx = 0; xx < 4; xx++) {
            float a = bias;
#pragma unroll
            for (int dy = 0; dy < 3; dy++) {
                a = fmaf(wsm[c16 * 9 + dy * 3 + 0], rr[dy][xx + 0], a);
                a = fmaf(wsm[c16 * 9 + dy * 3 + 1], rr[dy][xx + 1], a);
                a = fmaf(wsm[c16 * 9 + dy * 3 + 2], rr[dy][xx + 2], a);
            }
            o[xx] = a;
            ssq[c16] = fmaf(a, a, ssq[c16]);
        }
        if (c16 < 8) {
#pragma unroll
            for (int xx = 0; xx < 4; xx++) dvq[c16][xx] = o[xx];
        } else {
            int j = c16 - 8;
#pragma unroll
            for (int i = 0; i < 8; i++) {
                float s = gacc[i * 8 + j];
                s = fmaf(dvq[i][0], o[0], s);
                s = fmaf(dvq[i][1], o[1], s);
                s = fmaf(dvq[i][2], o[2], s);
                s = fmaf(dvq[i][3], o[3], s);
                gacc[i * 8 + j] = s;
            }
        }
    }

    __syncthreads();   // smem reuse for reduction
    float* red = sm;
    const int w = tid >> 5, lane = tid & 31;
#pragma unroll
    for (int v = 0; v < 64; v++) {
        float s = gacc[v];
#pragma unroll
        for (int off = 16; off; off >>= 1) s += __shfl_xor_sync(0xffffffffu, s, off);
        if (lane == 0) red[w * 80 + v] = s;
    }
#pragma unroll
    for (int v = 0; v < 16; v++) {
        float s = ssq[v];
#pragma unroll
        for (int off = 16; off; off >>= 1) s += __shfl_xor_sync(0xffffffffu, s, off);
        if (lane == 0) red[w * 80 + 64 + v] = s;
    }
    __syncthreads();
    if (tid < 80) {
        float s = 0.0f;
#pragma unroll
        for (int w2 = 0; w2 < 8; w2++) s += red[w2 * 80 + tid];
        if (tid < 64) atomicAdd(&g_gram[bh * 64 + tid], s);
        else {
            int c16 = tid - 64;
            int ch = (c16 < 8) ? h * 8 + c16 : 64 + h * 8 + (c16 - 8);
            atomicAdd(&g_sumsq[b * CQK + ch], s);
        }
    }
}

// ---------------- K4: softmax + M_b -------------------------------------------
__global__ void k_attn(const float* __restrict__ w_proj,
                       const float* __restrict__ temperature) {
    __shared__ float attn[B * HEADS * 8 * 8];
    int tid = threadIdx.x;
    int b = tid >> 6, h = (tid >> 3) & 7, i = tid & 7;

    float nq = fmaxf(sqrtf(g_sumsq[b * CQK + h * 8 + i]), 1e-12f);
    float temp = temperature[h];
    float row[8];
    float mx = -1e30f;
#pragma unroll
    for (int j = 0; j < 8; j++) {
        float nk = fmaxf(sqrtf(g_sumsq[b * CQK + 64 + h * 8 + j]), 1e-12f);
        float v = g_gram[((b * 8 + h) * 8 + i) * 8 + j] / (nq * nk) * temp;
        row[j] = v;
        mx = fmaxf(mx, v);
    }
    float s = 0.0f;
#pragma unroll
    for (int j = 0; j < 8; j++) { row[j] = expf(row[j] - mx); s += row[j]; }
    float inv = 1.0f / s;
#pragma unroll
    for (int j = 0; j < 8; j++) attn[((b * 8 + h) * 8 + i) * 8 + j] = row[j] * inv;
    __syncthreads();

    for (int e = tid; e < B * 64 * 64; e += 256) {
        int b2 = e >> 12, oc = (e >> 6) & 63, d = e & 63;
        int h2 = d >> 3, j = d & 7;
        float s2 = 0.0f;
#pragma unroll
        for (int i2 = 0; i2 < 8; i2++)
            s2 += w_proj[oc * 64 + h2 * 8 + i2] * attn[((b2 * 8 + h2) * 8 + i2) * 8 + j];
        g_M[e] = s2;
    }
}

// ---------------- K3: tf32 conv5x5 + gate + epilogue ---------------------------
#define YSTRIDE 408
#define WSTRIDE 72
#define VSTRIDE 68
#define WSM_OFF (32 * YSTRIDE)                 // 13056
#define MSM_OFF (WSM_OFF + 3 * 32 * WSTRIDE)   // 19968 (3-stage weight ring)

__global__ __launch_bounds__(256, 2)
void k_conv5_out(const float* __restrict__ x,
                 const float* __restrict__ b_proj,
                 float* __restrict__ out) {
    extern __shared__ float sm[];
    float* ysm = sm;                 // 32 * 408
    float* wsm = sm + WSM_OFF;       // 3 * 32 * 72
    float* Msm = sm + MSM_OFF;       // 64 * 72

    const int b = blockIdx.z;
    const int tx0 = blockIdx.x * 16, ty0 = blockIdx.y * 16;
    const int tid = threadIdx.x;
    const int w = tid >> 5, lane = tid & 31;
    const int g = lane >> 2, t4 = lane & 3;

    for (int i = tid; i < 4096; i += 256) {
        int ch = i & 63, oc = i >> 6;
        Msm[ch * WSTRIDE + oc] = to_tf32(g_M[b * 4096 + i]);
    }

    float acc[2][8][4];
#pragma unroll
    for (int m = 0; m < 2; m++)
#pragma unroll
        for (int n = 0; n < 8; n++)
#pragma unroll
            for (int j = 0; j < 4; j++) acc[m][n][j] = 0.0f;

    const uint32_t* ysmu = (const uint32_t*)ysm;

    for (int icc = 0; icc < 2; icc++) {
        if (icc) __syncthreads();   // protect ysm/wsm reuse across chunks
        for (int i = tid; i < 32 * 400; i += 256) {
            int ic = i / 400;
            int rem = i - ic * 400;
            int r = rem / 20, cc = rem - r * 20;
            int gy = ty0 - 2 + r, gx = tx0 - 2 + cc;
            float v = 0.0f;
            if (gy >= 0 && gy < HDIM && gx >= 0 && gx < WDIM)
                v = g_y[(size_t)(b * 64 + icc * 32 + ic) * HW + gy * WDIM + gx];
            ysm[ic * YSTRIDE + r * 20 + cc] = v;
        }
        {
            uint32_t base = (uint32_t)__cvta_generic_to_shared(wsm);
            const float* src = g_Wt + icc * 2048;
            for (int i = tid * 4; i < 2048; i += 1024) {
                int k = i >> 6, oc = i & 63;
                cp_async16(base + (uint32_t)(k * WSTRIDE + oc) * 4u, src + i);
            }
            asm volatile("cp.async.commit_group;");
        }

        for (int t = 0; t < 25; t++) {
            const float* wbuf = wsm + (t % 3) * (32 * WSTRIDE);
            if (t + 1 < 25) {
                float* nbuf = wsm + ((t + 1) % 3) * (32 * WSTRIDE);
                uint32_t base = (uint32_t)__cvta_generic_to_shared(nbuf);
                const float* src = g_Wt + (t + 1) * 4096 + icc * 2048;
                for (int i = tid * 4; i < 2048; i += 1024) {
                    int k = i >> 6, oc = i & 63;
                    cp_async16(base + (uint32_t)(k * WSTRIDE + oc) * 4u, src + i);
                }
                asm volatile("cp.async.commit_group;");
                asm volatile("cp.async.wait_group 1;");
            } else {
                asm volatile("cp.async.wait_group 0;");
            }
            __syncthreads();

            const int dy = t / 5, dx = t - dy * 5;
            const uint32_t* wbu = (const uint32_t*)wbuf;
            const int ro0 = (2 * w + dy) * 20 + dx + g;

#pragma unroll
            for (int ks = 0; ks < 4; ks++) {
                int ic = ks * 8 + t4;
                int abase = ic * YSTRIDE + ro0;
                uint32_t a0[4], a1[4];
                a0[0] = ysmu[abase];
                a0[1] = ysmu[abase + 8];
                a0[2] = ysmu[abase + 4 * YSTRIDE];
                a0[3] = ysmu[abase + 4 * YSTRIDE + 8];
                a1[0] = ysmu[abase + 20];
                a1[1] = ysmu[abase + 28];
                a1[2] = ysmu[abase + 4 * YSTRIDE + 20];
                a1[3] = ysmu[abase + 4 * YSTRIDE + 28];
                int bbase = ic * WSTRIDE + g;
#pragma unroll
                for (int n = 0; n < 8; n++) {
                    uint32_t bb[2];
                    bb[0] = wbu[bbase + n * 8];
                    bb[1] = wbu[bbase + 4 * WSTRIDE + n * 8];
                    mma_tf32(acc[0][n], a0, bb);
                    mma_tf32(acc[1][n], a1, bb);
                }
            }
        }
    }
    __syncthreads();   // all mma done before vv staging overwrites ysm

    float* vvsm = sm;
#pragma unroll
    for (int m = 0; m < 2; m++) {
        int py = 2 * w + m;
        int gy = ty0 + py;
#pragma unroll
        for (int n = 0; n < 8; n++) {
#pragma unroll
            for (int j = 0; j < 4; j++) {
                int px = g + ((j >> 1) << 3);
                int ch = n * 8 + t4 * 2 + (j & 1);
                float xv = x[(size_t)(b * 64 + ch) * HW + gy * WDIM + tx0 + px];
                float a = acc[m][n][j];
                float sg = 1.0f / (1.0f + __expf(-a));
                vvsm[(py * 16 + px) * VSTRIDE + ch] = to_tf32(xv * (1.0f + sg));
                acc[m][n][j] = 0.0f;
            }
        }
    }
    __syncthreads();

    const uint32_t* vvu = (const uint32_t*)vvsm;
    const uint32_t* Msu = (const uint32_t*)Msm;
    const int p0 = 32 * w + g;
#pragma unroll
    for (int ks = 0; ks < 8; ks++) {
        int ch = ks * 8 + t4;
        uint32_t a0[4], a1[4];
        a0[0] = vvu[p0 * VSTRIDE + ch];
        a0[1] = vvu[(p0 + 8) * VSTRIDE + ch];
        a0[2] = vvu[p0 * VSTRIDE + ch + 4];
        a0[3] = vvu[(p0 + 8) * VSTRIDE + ch + 4];
        a1[0] = vvu[(p0 + 16) * VSTRIDE + ch];
        a1[1] = vvu[(p0 + 24) * VSTRIDE + ch];
        a1[2] = vvu[(p0 + 16) * VSTRIDE + ch + 4];
        a1[3] = vvu[(p0 + 24) * VSTRIDE + ch + 4];
        int bbase = ch * WSTRIDE + g;
#pragma unroll
        for (int n = 0; n < 8; n++) {
            uint32_t bb[2];
            bb[0] = Msu[bbase + n * 8];
            bb[1] = Msu[bbase + 4 * WSTRIDE + n * 8];
            mma_tf32(acc[0][n], a0, bb);
            mma_tf32(acc[1][n], a1, bb);
        }
    }

#pragma unroll
    for (int m = 0; m < 2; m++) {
        int gy = ty0 + 2 * w + m;
#pragma unroll
        for (int n = 0; n < 8; n++) {
#pragma unroll
            for (int j = 0; j < 4; j++) {
                int px = g + ((j >> 1) << 3);
                int oc = n * 8 + t4 * 2 + (j & 1);
                out[(size_t)(b * 64 + oc) * HW + gy * WDIM + tx0 + px] =
                    acc[m][n][j] + __ldg(&b_proj[oc]);
            }
        }
    }
}

// ---------------- launch ------------------------------------------------------
extern "C" void kernel_launch(void* const* d_in, const int* in_sizes, int n_in,
                              void* d_out, int out_size) {
    const float* x      = (const float*)d_in[0];
    const float* w_qkv  = (const float*)d_in[1];
    const float* b_qkv  = (const float*)d_in[2];
    const float* w_dw   = (const float*)d_in[3];
    const float* b_dw   = (const float*)d_in[4];
    const float* w_proj = (const float*)d_in[5];
    const float* b_proj = (const float*)d_in[6];
    const float* temp   = (const float*)d_in[7];
    const float* w_m1   = (const float*)d_in[8];
    const float* bn_g   = (const float*)d_in[9];
    const float* bn_b   = (const float*)d_in[10];
    const float* bn_m   = (const float*)d_in[11];
    const float* bn_v   = (const float*)d_in[12];
    const float* w_m2   = (const float*)d_in[13];
    float* out = (float*)d_out;

    size_t smem_k0 = (size_t)(64 * PSTR + 64 * OSTR + 384) * sizeof(float);   // ~87.5 KB
    size_t smem_dg = (size_t)(16 * CST + 160) * sizeof(float);                // ~79 KB
    size_t smem_k3 = (size_t)(MSM_OFF + 64 * WSTRIDE) * sizeof(float);        // ~96 KB
    cudaFuncSetAttribute(k_pointwise, cudaFuncAttributeMaxDynamicSharedMemorySize,
                         (int)smem_k0);
    cudaFuncSetAttribute(k_dwgram, cudaFuncAttributeMaxDynamicSharedMemorySize,
                         (int)smem_dg);
    cudaFuncSetAttribute(k_conv5_out, cudaFuncAttributeMaxDynamicSharedMemorySize,
                         (int)smem_k3);

    k_zero<<<8, 256>>>();
    k_wt<<<400, 256>>>(w_m2);
    k_pointwise<<<dim3(HW / 128, B), 128, smem_k0>>>(x, w_qkv, b_qkv, w_m1,
                                                     bn_g, bn_b, bn_m, bn_v);
    k_dwgram<<<dim3(8, 8, B * HEADS), 256, smem_dg>>>(w_dw, b_dw);
    k_attn<<<1, 256>>>(w_proj, temp);
    k_conv5_out<<<dim3(16, 16, B), 256, smem_k3>>>(x, b_proj, out);
}

// round 5
// speedup vs baseline: 1.0255x; 1.0255x over previous
#include <cuda_runtime.h>
#include <cuda_bf16.h>
#include <math.h>
#include <stdint.h>

#define B 4
#define C 64
#define CQK 128
#define HDIM 256
#define WDIM 256
#define HW 65536
#define HEADS 8

// ---------------- scratch ----------------------------------------------------
__device__ __nv_bfloat16 g_qk_pre[(size_t)B * CQK * HW];  // bf16: q/k pre-dw
__device__ float g_y[(size_t)B * C * HW];                 // fp32 (tf32-rounded)
__device__ float g_sumsq[B * CQK];
__device__ float g_gram[B * HEADS * 8 * 8];
__device__ float g_M[B * C * C];
__device__ float g_Wt[25 * 64 * 64];

// ---------------- helpers -----------------------------------------------------
__device__ __forceinline__ float to_tf32(float v) {
    uint32_t u;
    asm("cvt.rna.tf32.f32 %0, %1;" : "=r"(u) : "f"(v));
    return __uint_as_float(u);
}

__device__ __forceinline__ void mma_tf32(float* d, const uint32_t* a, const uint32_t* b) {
    asm volatile(
        "mma.sync.aligned.m16n8k8.row.col.f32.tf32.tf32.f32 "
        "{%0,%1,%2,%3}, {%4,%5,%6,%7}, {%8,%9}, {%0,%1,%2,%3};"
        : "+f"(d[0]), "+f"(d[1]), "+f"(d[2]), "+f"(d[3])
        : "r"(a[0]), "r"(a[1]), "r"(a[2]), "r"(a[3]), "r"(b[0]), "r"(b[1]));
}

__device__ __forceinline__ void cp_async16(uint32_t daddr, const void* src) {
    asm volatile("cp.async.cg.shared.global [%0], [%1], 16;" :: "r"(daddr), "l"(src));
}

// ---------------- K_zero ------------------------------------------------------
__global__ void k_zero() {
    int i = blockIdx.x * blockDim.x + threadIdx.x;
    if (i < B * CQK) g_sumsq[i] = 0.0f;
    if (i < B * HEADS * 64) g_gram[i] = 0.0f;
}

// ---------------- K_wt --------------------------------------------------------
__global__ void k_wt(const float* __restrict__ w_m2) {
    int i = blockIdx.x * 256 + threadIdx.x;
    if (i < 25 * 4096) {
        int t = i / 4096;
        int rem = i & 4095;
        int ic = rem >> 6, oc = rem & 63;
        g_Wt[i] = to_tf32(w_m2[(oc * 64 + ic) * 25 + t]);
    }
}

// ---------------- K0: tf32-MMA fused 1x1 convs (R3 shape, bf16 qk stores) -----
// 256 threads, M=128 px (1 frag/warp), N=192 (24 frags), K=64.
#define PSTR 136
#define OSTR 200

__global__ __launch_bounds__(256)
void k_pointwise(const float* __restrict__ x,
                 const float* __restrict__ w_qkv,
                 const float* __restrict__ b_qkv,
                 const float* __restrict__ w_m1,
                 const float* __restrict__ bn_g,
                 const float* __restrict__ bn_b,
                 const float* __restrict__ bn_m,
                 const float* __restrict__ bn_v) {
    extern __shared__ float sm[];
    float* xs     = sm;                  // 64 * 136
    float* ws     = xs + 64 * PSTR;      // 64 * 200
    float* sscale = ws + 64 * OSTR;      // 192
    float* sshift = sscale + 192;        // 192

    const int tid = threadIdx.x;
    const int b = blockIdx.y;
    const int p0 = blockIdx.x * 128;

    for (int i = tid; i < 128 * 64; i += 256) {
        int oc = i >> 6, ic = i & 63;
        ws[ic * OSTR + oc] = to_tf32(w_qkv[i]);
    }
    for (int i = tid; i < 64 * 64; i += 256) {
        int oc = i >> 6, ic = i & 63;
        ws[ic * OSTR + 128 + oc] = to_tf32(w_m1[i]);
    }
    for (int i = tid; i < 192; i += 256) {
        if (i < 128) { sscale[i] = 1.0f; sshift[i] = b_qkv[i]; }
        else {
            int cc = i - 128;
            float s = bn_g[cc] * rsqrtf(bn_v[cc] + 1e-5f);
            sscale[i] = s;
            sshift[i] = bn_b[cc] - bn_m[cc] * s;
        }
    }
    for (int i = tid * 4; i < 64 * 128; i += 1024) {
        int ic = i >> 7, px = i & 127;
        float4 v = *(const float4*)(x + (size_t)(b * 64 + ic) * HW + p0 + px);
        float* d = xs + ic * PSTR + px;
        d[0] = to_tf32(v.x); d[1] = to_tf32(v.y);
        d[2] = to_tf32(v.z); d[3] = to_tf32(v.w);
    }
    __syncthreads();

    const int w = tid >> 5, lane = tid & 31;
    const int g = lane >> 2, t4 = lane & 3;

    float acc[24][4];
#pragma unroll
    for (int n = 0; n < 24; n++)
#pragma unroll
        for (int j = 0; j < 4; j++) acc[n][j] = 0.0f;

    const uint32_t* xsu = (const uint32_t*)xs;
    const uint32_t* wsu = (const uint32_t*)ws;
    const int mrow = w * 16 + g;

#pragma unroll
    for (int ks = 0; ks < 8; ks++) {
        int ic = ks * 8 + t4;
        uint32_t a[4];
        a[0] = xsu[ic * PSTR + mrow];
        a[1] = xsu[ic * PSTR + mrow + 8];
        a[2] = xsu[(ic + 4) * PSTR + mrow];
        a[3] = xsu[(ic + 4) * PSTR + mrow + 8];
        int bb0 = ic * OSTR + g;
#pragma unroll
        for (int n = 0; n < 24; n++) {
            uint32_t bb[2];
            bb[0] = wsu[bb0 + n * 8];
            bb[1] = wsu[bb0 + 4 * OSTR + n * 8];
            mma_tf32(acc[n], a, bb);
        }
    }

#pragma unroll
    for (int n = 0; n < 24; n++) {
#pragma unroll
        for (int j = 0; j < 4; j++) {
            int oc = n * 8 + t4 * 2 + (j & 1);
            int px = p0 + w * 16 + g + ((j >> 1) << 3);
            float v = acc[n][j] * sscale[oc] + sshift[oc];
            if (oc < 128)
                g_qk_pre[(size_t)(b * 128 + oc) * HW + px] = __float2bfloat16(v);
            else
                g_y[(size_t)(b * 64 + oc - 128) * HW + px] = to_tf32(v);
        }
    }
}

// ---------------- K1: fused depthwise3x3 + gram + sumsq (bf16 input) ----------
// grid (8, 8, B*HEADS), 256 threads. Tile 32x32, 16 channels (8 q + 8 k).
#define RST 36
#define CST (34 * RST)   // 1224

__global__ __launch_bounds__(256)
void k_dwgram(const float* __restrict__ w_dw,
              const float* __restrict__ b_dw) {
    extern __shared__ float sm[];          // 16 * 1224
    float* wsm = sm + 16 * CST;            // 144
    float* bsm = wsm + 144;                // 16

    const int bh = blockIdx.z;
    const int b = bh >> 3, h = bh & 7;
    const int tx0 = blockIdx.x * 32, ty0 = blockIdx.y * 32;
    const int tid = threadIdx.x;

    for (int i = tid; i < 144; i += 256) {
        int c16 = i / 9, t = i - c16 * 9;
        int ch = (c16 < 8) ? h * 8 + c16 : 64 + h * 8 + (c16 - 8);
        wsm[i] = w_dw[ch * 9 + t];
    }
    if (tid < 16) {
        int ch = (tid < 8) ? h * 8 + tid : 64 + h * 8 + (tid - 8);
        bsm[tid] = b_dw[tid < 8 ? h * 8 + tid : 64 + h * 8 + (tid - 8)];
        (void)ch;
    }

    const bool interior = (tx0 > 0) && (ty0 > 0) && (tx0 < 224) && (ty0 < 224);
#pragma unroll 1
    for (int c16 = 0; c16 < 16; c16++) {
        int ch = (c16 < 8) ? h * 8 + c16 : 64 + h * 8 + (c16 - 8);
        const __nv_bfloat16* src =
            g_qk_pre + ((size_t)b * CQK + ch) * HW + (ty0 - 1) * WDIM + (tx0 - 1);
        float* dst = sm + c16 * CST;
        if (interior) {
#pragma unroll
            for (int k = 0; k < 5; k++) {
                int i = tid + k * 256;
                if (i < 1156) {
                    int r = i / 34, cc = i - r * 34;
                    dst[r * RST + cc] = __bfloat162float(src[r * WDIM + cc]);
                }
            }
        } else {
#pragma unroll
            for (int k = 0; k < 5; k++) {
                int i = tid + k * 256;
                if (i < 1156) {
                    int r = i / 34, cc = i - r * 34;
                    int gy = ty0 - 1 + r, gx = tx0 - 1 + cc;
                    float v = 0.0f;
                    if (gy >= 0 && gy < HDIM && gx >= 0 && gx < WDIM)
                        v = __bfloat162float(src[r * WDIM + cc]);
                    dst[r * RST + cc] = v;
                }
            }
        }
    }
    __syncthreads();

    const int q = tid & 7, py = tid >> 3;
    const int base0 = py * RST + 4 * q;   // storage col 4q == input col 4q-1

    float dvq[8][4], gacc[64], ssq[16];
#pragma unroll
    for (int i = 0; i < 64; i++) gacc[i] = 0.0f;
#pragma unroll
    for (int i = 0; i < 16; i++) ssq[i] = 0.0f;

#pragma unroll
    for (int c16 = 0; c16 < 16; c16++) {
        const float4* rp = (const float4*)(sm + c16 * CST + base0);
        float rr[3][6];
#pragma unroll
        for (int dy = 0; dy < 3; dy++) {
            float4 a = rp[dy * (RST / 4)];
            float4 bb = rp[dy * (RST / 4) + 1];
            rr[dy][0] = a.x; rr[dy][1] = a.y; rr[dy][2] = a.z;
            rr[dy][3] = a.w; rr[dy][4] = bb.x; rr[dy][5] = bb.y;
        }
        float o[4];
        float bias = bsm[c16];
#pragma unroll
        for (int xx = 0; xx < 4; xx++) {
            float a = bias;
#pragma unroll
            for (int dy = 0; dy < 3; dy++) {
                a = fmaf(wsm[c16 * 9 + dy * 3 + 0], rr[dy][xx + 0], a);
                a = fmaf(wsm[c16 * 9 + dy * 3 + 1], rr[dy][xx + 1], a);
                a = fmaf(wsm[c16 * 9 + dy * 3 + 2], rr[dy][xx + 2], a);
            }
            o[xx] = a;
            ssq[c16] = fmaf(a, a, ssq[c16]);
        }
        if (c16 < 8) {
#pragma unroll
            for (int xx = 0; xx < 4; xx++) dvq[c16][xx] = o[xx];
        } else {
            int j = c16 - 8;
#pragma unroll
            for (int i = 0; i < 8; i++) {
                float s = gacc[i * 8 + j];
                s = fmaf(dvq[i][0], o[0], s);
                s = fmaf(dvq[i][1], o[1], s);
                s = fmaf(dvq[i][2], o[2], s);
                s = fmaf(dvq[i][3], o[3], s);
                gacc[i * 8 + j] = s;
            }
        }
    }

    __syncthreads();
    float* red = sm;
    const int w = tid >> 5, lane = tid & 31;
#pragma unroll
    for (int v = 0; v < 64; v++) {
        float s = gacc[v];
#pragma unroll
        for (int off = 16; off; off >>= 1) s += __shfl_xor_sync(0xffffffffu, s, off);
        if (lane == 0) red[w * 80 + v] = s;
    }
#pragma unroll
    for (int v = 0; v < 16; v++) {
        float s = ssq[v];
#pragma unroll
        for (int off = 16; off; off >>= 1) s += __shfl_xor_sync(0xffffffffu, s, off);
        if (lane == 0) red[w * 80 + 64 + v] = s;
    }
    __syncthreads();
    if (tid < 80) {
        float s = 0.0f;
#pragma unroll
        for (int w2 = 0; w2 < 8; w2++) s += red[w2 * 80 + tid];
        if (tid < 64) atomicAdd(&g_gram[bh * 64 + tid], s);
        else {
            int c16 = tid - 64;
            int ch = (c16 < 8) ? h * 8 + c16 : 64 + h * 8 + (c16 - 8);
            atomicAdd(&g_sumsq[b * CQK + ch], s);
        }
    }
}

// ---------------- K4: softmax + M_b -------------------------------------------
__global__ void k_attn(const float* __restrict__ w_proj,
                       const float* __restrict__ temperature) {
    __shared__ float attn[B * HEADS * 8 * 8];
    int tid = threadIdx.x;
    int b = tid >> 6, h = (tid >> 3) & 7, i = tid & 7;

    float nq = fmaxf(sqrtf(g_sumsq[b * CQK + h * 8 + i]), 1e-12f);
    float temp = temperature[h];
    float row[8];
    float mx = -1e30f;
#pragma unroll
    for (int j = 0; j < 8; j++) {
        float nk = fmaxf(sqrtf(g_sumsq[b * CQK + 64 + h * 8 + j]), 1e-12f);
        float v = g_gram[((b * 8 + h) * 8 + i) * 8 + j] / (nq * nk) * temp;
        row[j] = v;
        mx = fmaxf(mx, v);
    }
    float s = 0.0f;
#pragma unroll
    for (int j = 0; j < 8; j++) { row[j] = expf(row[j] - mx); s += row[j]; }
    float inv = 1.0f / s;
#pragma unroll
    for (int j = 0; j < 8; j++) attn[((b * 8 + h) * 8 + i) * 8 + j] = row[j] * inv;
    __syncthreads();

    for (int e = tid; e < B * 64 * 64; e += 256) {
        int b2 = e >> 12, oc = (e >> 6) & 63, d = e & 63;
        int h2 = d >> 3, j = d & 7;
        float s2 = 0.0f;
#pragma unroll
        for (int i2 = 0; i2 < 8; i2++)
            s2 += w_proj[oc * 64 + h2 * 8 + i2] * attn[((b2 * 8 + h2) * 8 + i2) * 8 + j];
        g_M[e] = s2;
    }
}

// ---------------- K3: tf32 conv5x5 + gate + epilogue ---------------------------
#define YSTRIDE 408
#define WSTRIDE 72
#define VSTRIDE 68
#define WSM_OFF (32 * YSTRIDE)
#define MSM_OFF (WSM_OFF + 3 * 32 * WSTRIDE)

__global__ __launch_bounds__(256, 2)
void k_conv5_out(const float* __restrict__ x,
                 const float* __restrict__ b_proj,
                 float* __restrict__ out) {
    extern __shared__ float sm[];
    float* ysm = sm;
    float* wsm = sm + WSM_OFF;
    float* Msm = sm + MSM_OFF;

    const int b = blockIdx.z;
    const int tx0 = blockIdx.x * 16, ty0 = blockIdx.y * 16;
    const int tid = threadIdx.x;
    const int w = tid >> 5, lane = tid & 31;
    const int g = lane >> 2, t4 = lane & 3;

    for (int i = tid; i < 4096; i += 256) {
        int ch = i & 63, oc = i >> 6;
        Msm[ch * WSTRIDE + oc] = to_tf32(g_M[b * 4096 + i]);
    }

    float acc[2][8][4];
#pragma unroll
    for (int m = 0; m < 2; m++)
#pragma unroll
        for (int n = 0; n < 8; n++)
#pragma unroll
            for (int j = 0; j < 4; j++) acc[m][n][j] = 0.0f;

    const uint32_t* ysmu = (const uint32_t*)ysm;

    for (int icc = 0; icc < 2; icc++) {
        if (icc) __syncthreads();
        for (int i = tid; i < 32 * 400; i += 256) {
            int ic = i / 400;
            int rem = i - ic * 400;
            int r = rem / 20, cc = rem - r * 20;
            int gy = ty0 - 2 + r, gx = tx0 - 2 + cc;
            float v = 0.0f;
            if (gy >= 0 && gy < HDIM && gx >= 0 && gx < WDIM)
                v = g_y[(size_t)(b * 64 + icc * 32 + ic) * HW + gy * WDIM + gx];
            ysm[ic * YSTRIDE + r * 20 + cc] = v;
        }
        {
            uint32_t base = (uint32_t)__cvta_generic_to_shared(wsm);
            const float* src = g_Wt + icc * 2048;
            for (int i = tid * 4; i < 2048; i += 1024) {
                int k = i >> 6, oc = i & 63;
                cp_async16(base + (uint32_t)(k * WSTRIDE + oc) * 4u, src + i);
            }
            asm volatile("cp.async.commit_group;");
        }

        for (int t = 0; t < 25; t++) {
            const float* wbuf = wsm + (t % 3) * (32 * WSTRIDE);
            if (t + 1 < 25) {
                float* nbuf = wsm + ((t + 1) % 3) * (32 * WSTRIDE);
                uint32_t base = (uint32_t)__cvta_generic_to_shared(nbuf);
                const float* src = g_Wt + (t + 1) * 4096 + icc * 2048;
                for (int i = tid * 4; i < 2048; i += 1024) {
                    int k = i >> 6, oc = i & 63;
                    cp_async16(base + (uint32_t)(k * WSTRIDE + oc) * 4u, src + i);
                }
                asm volatile("cp.async.commit_group;");
                asm volatile("cp.async.wait_group 1;");
            } else {
                asm volatile("cp.async.wait_group 0;");
            }
            __syncthreads();

            const int dy = t / 5, dx = t - dy * 5;
            const uint32_t* wbu = (const uint32_t*)wbuf;
            const int ro0 = (2 * w + dy) * 20 + dx + g;

#pragma unroll
            for (int ks = 0; ks < 4; ks++) {
                int ic = ks * 8 + t4;
                int abase = ic * YSTRIDE + ro0;
                uint32_t a0[4], a1[4];
                a0[0] = ysmu[abase];
                a0[1] = ysmu[abase + 8];
                a0[2] = ysmu[abase + 4 * YSTRIDE];
                a0[3] = ysmu[abase + 4 * YSTRIDE + 8];
                a1[0] = ysmu[abase + 20];
                a1[1] = ysmu[abase + 28];
                a1[2] = ysmu[abase + 4 * YSTRIDE + 20];
                a1[3] = ysmu[abase + 4 * YSTRIDE + 28];
                int bbase = ic * WSTRIDE + g;
#pragma unroll
                for (int n = 0; n < 8; n++) {
                    uint32_t bb[2];
                    bb[0] = wbu[bbase + n * 8];
                    bb[1] = wbu[bbase + 4 * WSTRIDE + n * 8];
                    mma_tf32(acc[0][n], a0, bb);
                    mma_tf32(acc[1][n], a1, bb);
                }
            }
        }
    }
    __syncthreads();

    float* vvsm = sm;
#pragma unroll
    for (int m = 0; m < 2; m++) {
        int py = 2 * w + m;
        int gy = ty0 + py;
#pragma unroll
        for (int n = 0; n < 8; n++) {
#pragma unroll
            for (int j = 0; j < 4; j++) {
                int px = g + ((j >> 1) << 3);
                int ch = n * 8 + t4 * 2 + (j & 1);
                float xv = x[(size_t)(b * 64 + ch) * HW + gy * WDIM + tx0 + px];
                float a = acc[m][n][j];
                float sg = 1.0f / (1.0f + __expf(-a));
                vvsm[(py * 16 + px) * VSTRIDE + ch] = to_tf32(xv * (1.0f + sg));
                acc[m][n][j] = 0.0f;
            }
        }
    }
    __syncthreads();

    const uint32_t* vvu = (const uint32_t*)vvsm;
    const uint32_t* Msu = (const uint32_t*)Msm;
    const int p0 = 32 * w + g;
#pragma unroll
    for (int ks = 0; ks < 8; ks++) {
        int ch = ks * 8 + t4;
        uint32_t a0[4], a1[4];
        a0[0] = vvu[p0 * VSTRIDE + ch];
        a0[1] = vvu[(p0 + 8) * VSTRIDE + ch];
        a0[2] = vvu[p0 * VSTRIDE + ch + 4];
        a0[3] = vvu[(p0 + 8) * VSTRIDE + ch + 4];
        a1[0] = vvu[(p0 + 16) * VSTRIDE + ch];
        a1[1] = vvu[(p0 + 24) * VSTRIDE + ch];
        a1[2] = vvu[(p0 + 16) * VSTRIDE + ch + 4];
        a1[3] = vvu[(p0 + 24) * VSTRIDE + ch + 4];
        int bbase = ch * WSTRIDE + g;
#pragma unroll
        for (int n = 0; n < 8; n++) {
            uint32_t bb[2];
            bb[0] = Msu[bbase + n * 8];
            bb[1] = Msu[bbase + 4 * WSTRIDE + n * 8];
            mma_tf32(acc[0][n], a0, bb);
            mma_tf32(acc[1][n], a1, bb);
        }
    }

#pragma unroll
    for (int m = 0; m < 2; m++) {
        int gy = ty0 + 2 * w + m;
#pragma unroll
        for (int n = 0; n < 8; n++) {
#pragma unroll
            for (int j = 0; j < 4; j++) {
                int px = g + ((j >> 1) << 3);
                int oc = n * 8 + t4 * 2 + (j & 1);
                out[(size_t)(b * 64 + oc) * HW + gy * WDIM + tx0 + px] =
                    acc[m][n][j] + __ldg(&b_proj[oc]);
            }
        }
    }
}

// ---------------- launch ------------------------------------------------------
extern "C" void kernel_launch(void* const* d_in, const int* in_sizes, int n_in,
                              void* d_out, int out_size) {
    const float* x      = (const float*)d_in[0];
    const float* w_qkv  = (const float*)d_in[1];
    const float* b_qkv  = (const float*)d_in[2];
    const float* w_dw   = (const float*)d_in[3];
    const float* b_dw   = (const float*)d_in[4];
    const float* w_proj = (const float*)d_in[5];
    const float* b_proj = (const float*)d_in[6];
    const float* temp   = (const float*)d_in[7];
    const float* w_m1   = (const float*)d_in[8];
    const float* bn_g   = (const float*)d_in[9];
    const float* bn_b   = (const float*)d_in[10];
    const float* bn_m   = (const float*)d_in[11];
    const float* bn_v   = (const float*)d_in[12];
    const float* w_m2   = (const float*)d_in[13];
    float* out = (float*)d_out;

    size_t smem_k0 = (size_t)(64 * PSTR + 64 * OSTR + 384) * sizeof(float);
    size_t smem_dg = (size_t)(16 * CST + 160) * sizeof(float);
    size_t smem_k3 = (size_t)(MSM_OFF + 64 * WSTRIDE) * sizeof(float);
    cudaFuncSetAttribute(k_pointwise, cudaFuncAttributeMaxDynamicSharedMemorySize,
                         (int)smem_k0);
    cudaFuncSetAttribute(k_dwgram, cudaFuncAttributeMaxDynamicSharedMemorySize,
                         (int)smem_dg);
    cudaFuncSetAttribute(k_conv5_out, cudaFuncAttributeMaxDynamicSharedMemorySize,
                         (int)smem_k3);

    k_zero<<<8, 256>>>();
    k_wt<<<400, 256>>>(w_m2);
    k_pointwise<<<dim3(HW / 128, B), 256, smem_k0>>>(x, w_qkv, b_qkv, w_m1,
                                                     bn_g, bn_b, bn_m, bn_v);
    k_dwgram<<<dim3(8, 8, B * HEADS), 256, smem_dg>>>(w_dw, b_dw);
    k_attn<<<1, 256>>>(w_proj, temp);
    k_conv5_out<<<dim3(16, 16, B), 256, smem_k3>>>(x, b_proj, out);
}

// round 6
// speedup vs baseline: 1.1690x; 1.1399x over previous
#include <cuda_runtime.h>
#include <cuda_bf16.h>
#include <math.h>
#include <stdint.h>

#define B 4
#define C 64
#define CQK 128
#define HDIM 256
#define WDIM 256
#define HW 65536
#define HEADS 8

// ---------------- scratch ----------------------------------------------------
__device__ __nv_bfloat16 g_qk_pre[(size_t)B * CQK * HW];  // bf16: q/k pre-dw
__device__ float g_y[(size_t)B * C * HW];                 // fp32 (tf32-rounded)
__device__ float g_sumsq[B * CQK];
__device__ float g_gram[B * HEADS * 8 * 8];
__device__ float g_M[B * C * C];
__device__ float g_Wt[25 * 64 * 64];

// ---------------- helpers -----------------------------------------------------
__device__ __forceinline__ float to_tf32(float v) {
    uint32_t u;
    asm("cvt.rna.tf32.f32 %0, %1;" : "=r"(u) : "f"(v));
    return __uint_as_float(u);
}

__device__ __forceinline__ void mma_tf32(float* d, const uint32_t* a, const uint32_t* b) {
    asm volatile(
        "mma.sync.aligned.m16n8k8.row.col.f32.tf32.tf32.f32 "
        "{%0,%1,%2,%3}, {%4,%5,%6,%7}, {%8,%9}, {%0,%1,%2,%3};"
        : "+f"(d[0]), "+f"(d[1]), "+f"(d[2]), "+f"(d[3])
        : "r"(a[0]), "r"(a[1]), "r"(a[2]), "r"(a[3]), "r"(b[0]), "r"(b[1]));
}

__device__ __forceinline__ void cp_async16(uint32_t daddr, const void* src) {
    asm volatile("cp.async.cg.shared.global [%0], [%1], 16;" :: "r"(daddr), "l"(src));
}

__device__ __forceinline__ float2 bf2f(uint32_t u) {
    float2 r;
    r.x = __uint_as_float(u << 16);
    r.y = __uint_as_float(u & 0xFFFF0000u);
    return r;
}

// ---------------- K_zero ------------------------------------------------------
__global__ void k_zero() {
    int i = blockIdx.x * blockDim.x + threadIdx.x;
    if (i < B * CQK) g_sumsq[i] = 0.0f;
    if (i < B * HEADS * 64) g_gram[i] = 0.0f;
}

// ---------------- K_wt --------------------------------------------------------
__global__ void k_wt(const float* __restrict__ w_m2) {
    int i = blockIdx.x * 256 + threadIdx.x;
    if (i < 25 * 4096) {
        int t = i / 4096;
        int rem = i & 4095;
        int ic = rem >> 6, oc = rem & 63;
        g_Wt[i] = to_tf32(w_m2[(oc * 64 + ic) * 25 + t]);
    }
}

// ---------------- K0: tf32-MMA fused 1x1 convs --------------------------------
#define PSTR 136
#define OSTR 200

__global__ __launch_bounds__(256)
void k_pointwise(const float* __restrict__ x,
                 const float* __restrict__ w_qkv,
                 const float* __restrict__ b_qkv,
                 const float* __restrict__ w_m1,
                 const float* __restrict__ bn_g,
                 const float* __restrict__ bn_b,
                 const float* __restrict__ bn_m,
                 const float* __restrict__ bn_v) {
    extern __shared__ float sm[];
    float* xs     = sm;
    float* ws     = xs + 64 * PSTR;
    float* sscale = ws + 64 * OSTR;
    float* sshift = sscale + 192;

    const int tid = threadIdx.x;
    const int b = blockIdx.y;
    const int p0 = blockIdx.x * 128;

    for (int i = tid; i < 128 * 64; i += 256) {
        int oc = i >> 6, ic = i & 63;
        ws[ic * OSTR + oc] = to_tf32(w_qkv[i]);
    }
    for (int i = tid; i < 64 * 64; i += 256) {
        int oc = i >> 6, ic = i & 63;
        ws[ic * OSTR + 128 + oc] = to_tf32(w_m1[i]);
    }
    for (int i = tid; i < 192; i += 256) {
        if (i < 128) { sscale[i] = 1.0f; sshift[i] = b_qkv[i]; }
        else {
            int cc = i - 128;
            float s = bn_g[cc] * rsqrtf(bn_v[cc] + 1e-5f);
            sscale[i] = s;
            sshift[i] = bn_b[cc] - bn_m[cc] * s;
        }
    }
    for (int i = tid * 4; i < 64 * 128; i += 1024) {
        int ic = i >> 7, px = i & 127;
        float4 v = *(const float4*)(x + (size_t)(b * 64 + ic) * HW + p0 + px);
        float* d = xs + ic * PSTR + px;
        d[0] = to_tf32(v.x); d[1] = to_tf32(v.y);
        d[2] = to_tf32(v.z); d[3] = to_tf32(v.w);
    }
    __syncthreads();

    const int w = tid >> 5, lane = tid & 31;
    const int g = lane >> 2, t4 = lane & 3;

    float acc[24][4];
#pragma unroll
    for (int n = 0; n < 24; n++)
#pragma unroll
        for (int j = 0; j < 4; j++) acc[n][j] = 0.0f;

    const uint32_t* xsu = (const uint32_t*)xs;
    const uint32_t* wsu = (const uint32_t*)ws;
    const int mrow = w * 16 + g;

#pragma unroll
    for (int ks = 0; ks < 8; ks++) {
        int ic = ks * 8 + t4;
        uint32_t a[4];
        a[0] = xsu[ic * PSTR + mrow];
        a[1] = xsu[ic * PSTR + mrow + 8];
        a[2] = xsu[(ic + 4) * PSTR + mrow];
        a[3] = xsu[(ic + 4) * PSTR + mrow + 8];
        int bb0 = ic * OSTR + g;
#pragma unroll
        for (int n = 0; n < 24; n++) {
            uint32_t bb[2];
            bb[0] = wsu[bb0 + n * 8];
            bb[1] = wsu[bb0 + 4 * OSTR + n * 8];
            mma_tf32(acc[n], a, bb);
        }
    }

#pragma unroll
    for (int n = 0; n < 24; n++) {
#pragma unroll
        for (int j = 0; j < 4; j++) {
            int oc = n * 8 + t4 * 2 + (j & 1);
            int px = p0 + w * 16 + g + ((j >> 1) << 3);
            float v = acc[n][j] * sscale[oc] + sshift[oc];
            if (oc < 128)
                g_qk_pre[(size_t)(b * 128 + oc) * HW + px] = __float2bfloat16(v);
            else
                g_y[(size_t)(b * 64 + oc - 128) * HW + px] = to_tf32(v);
        }
    }
}

// ---------------- K1: fused depthwise3x3 + gram + sumsq (3-phase) -------------
// grid (8, 8, B*HEADS), 256 threads, 3 CTAs/SM.
// Smem (uints): input bf16 [16 ch][34 rows][18 u] (CH_U pad 616),
//               dv bf16 [16 ch][512 u] (stride 516), wsm/bsm tail.
#define SR_U 18
#define CH_U 616
#define DV_OFF (16 * CH_U)          // 9856
#define DV_CH 516
#define WSM_U (DV_OFF + 16 * DV_CH) // 18112
#define BSM_U (WSM_U + 144)
#define TOT_U (BSM_U + 16)          // 18272 uints = 73088 B

__global__ __launch_bounds__(256, 3)
void k_dwgram(const float* __restrict__ w_dw,
              const float* __restrict__ b_dw) {
    extern __shared__ uint32_t smu[];
    float* wsm = (float*)(smu + WSM_U);
    float* bsm = (float*)(smu + BSM_U);

    const int bh = blockIdx.z;
    const int b = bh >> 3, h = bh & 7;
    const int tx0 = blockIdx.x * 32, ty0 = blockIdx.y * 32;
    const int tid = threadIdx.x;
    const int w = tid >> 5, lane = tid & 31;

    for (int i = tid; i < 144; i += 256) {
        int c16 = i / 9, t = i - c16 * 9;
        int ch = (c16 < 8) ? h * 8 + c16 : 64 + h * 8 + (c16 - 8);
        wsm[i] = w_dw[ch * 9 + t];
    }
    if (tid < 16) {
        int ch = (tid < 8) ? h * 8 + tid : 64 + h * 8 + (tid - 8);
        bsm[tid] = b_dw[ch];
    }

    // ---- stage input halo: 16 ch x 34 rows x 18 uints (36 bf16 from tx0-2) ----
    const __nv_bfloat16* gbase = g_qk_pre + (size_t)b * CQK * HW;
#pragma unroll
    for (int k = 0; k < 39; k++) {
        int idx = tid + k * 256;
        if (idx < 16 * 34 * SR_U) {
            int c16 = idx / (34 * SR_U);
            int rem = idx - c16 * (34 * SR_U);
            int r = rem / SR_U, cc = rem - r * SR_U;
            int ch = (c16 < 8) ? h * 8 + c16 : 64 + h * 8 + (c16 - 8);
            int gy = ty0 - 1 + r;
            int gx = tx0 - 2 + 2 * cc;            // even; pairs never straddle edge
            uint32_t v = 0;
            if (gy >= 0 && gy < HDIM && gx >= 0 && gx < WDIM)
                v = *(const uint32_t*)(gbase + (size_t)ch * HW + gy * WDIM + gx);
            smu[c16 * CH_U + r * SR_U + cc] = v;
        }
    }
    __syncthreads();

    // ---- phase A: depthwise for own 4-px strip, dv -> smem (bf16), ssq regs ---
    const int q = tid & 7, py = tid >> 3;
    float ssq[16];
#pragma unroll
    for (int i = 0; i < 16; i++) ssq[i] = 0.0f;

#pragma unroll
    for (int c16 = 0; c16 < 16; c16++) {
        // rows py..py+2, uints 2q..2q+3 (cols 4q..4q+7 rel. tx0-2)
        float f[3][8];
#pragma unroll
        for (int dy = 0; dy < 3; dy++) {
            const uint2* p2 = (const uint2*)(smu + c16 * CH_U + (py + dy) * SR_U + 2 * q);
            uint2 u01 = p2[0], u23 = p2[1];
            float2 a0 = bf2f(u01.x), a1 = bf2f(u01.y);
            float2 a2 = bf2f(u23.x), a3 = bf2f(u23.y);
            f[dy][0] = a0.x; f[dy][1] = a0.y; f[dy][2] = a1.x; f[dy][3] = a1.y;
            f[dy][4] = a2.x; f[dy][5] = a2.y; f[dy][6] = a3.x; f[dy][7] = a3.y;
        }
        float bias = bsm[c16];
        float o[4];
#pragma unroll
        for (int xx = 0; xx < 4; xx++) {
            float a = bias;
#pragma unroll
            for (int dy = 0; dy < 3; dy++) {
                a = fmaf(wsm[c16 * 9 + dy * 3 + 0], f[dy][xx + 1], a);
                a = fmaf(wsm[c16 * 9 + dy * 3 + 1], f[dy][xx + 2], a);
                a = fmaf(wsm[c16 * 9 + dy * 3 + 2], f[dy][xx + 3], a);
            }
            o[xx] = a;
            ssq[c16] = fmaf(a, a, ssq[c16]);
        }
        // store dv strip (4 px) as 2 packed bf16 uints
        uint2 dvu;
        __nv_bfloat162 p0 = __floats2bfloat162_rn(o[0], o[1]);
        __nv_bfloat162 p1 = __floats2bfloat162_rn(o[2], o[3]);
        dvu.x = *(uint32_t*)&p0;
        dvu.y = *(uint32_t*)&p1;
        *(uint2*)(smu + DV_OFF + c16 * DV_CH + py * 16 + 2 * q) = dvu;
    }
    __syncthreads();

    // ---- phase B: warp w accumulates gram row i=w over all 1024 px ------------
    float gacc[8];
#pragma unroll
    for (int j = 0; j < 8; j++) gacc[j] = 0.0f;

    const uint32_t* dvq = smu + DV_OFF + w * DV_CH;
    const uint32_t* dvk = smu + DV_OFF + 8 * DV_CH;
#pragma unroll
    for (int s = 0; s < 8; s++) {
        int ui = s * 64 + lane * 2;
        uint2 uq = *(const uint2*)(dvq + ui);
        float2 q01 = bf2f(uq.x), q23 = bf2f(uq.y);
#pragma unroll
        for (int j = 0; j < 8; j++) {
            uint2 uk = *(const uint2*)(dvk + j * DV_CH + ui);
            float2 k01 = bf2f(uk.x), k23 = bf2f(uk.y);
            float s2 = gacc[j];
            s2 = fmaf(q01.x, k01.x, s2);
            s2 = fmaf(q01.y, k01.y, s2);
            s2 = fmaf(q23.x, k23.x, s2);
            s2 = fmaf(q23.y, k23.y, s2);
            gacc[j] = s2;
        }
    }

    // ---- phase C: reductions ---------------------------------------------------
#pragma unroll
    for (int j = 0; j < 8; j++) {
        float s = gacc[j];
#pragma unroll
        for (int off = 16; off; off >>= 1) s += __shfl_xor_sync(0xffffffffu, s, off);
        if (lane == 0) atomicAdd(&g_gram[bh * 64 + w * 8 + j], s);
    }
    float* red = (float*)smu;   // input region free now
#pragma unroll
    for (int cidx = 0; cidx < 16; cidx++) {
        float s = ssq[cidx];
#pragma unroll
        for (int off = 16; off; off >>= 1) s += __shfl_xor_sync(0xffffffffu, s, off);
        if (lane == 0) red[w * 16 + cidx] = s;
    }
    __syncthreads();
    if (tid < 16) {
        float s = 0.0f;
#pragma unroll
        for (int w2 = 0; w2 < 8; w2++) s += red[w2 * 16 + tid];
        int ch = (tid < 8) ? h * 8 + tid : 64 + h * 8 + (tid - 8);
        atomicAdd(&g_sumsq[b * CQK + ch], s);
    }
}

// ---------------- K4: softmax + M_b -------------------------------------------
__global__ void k_attn(const float* __restrict__ w_proj,
                       const float* __restrict__ temperature) {
    __shared__ float attn[B * HEADS * 8 * 8];
    int tid = threadIdx.x;
    int b = tid >> 6, h = (tid >> 3) & 7, i = tid & 7;

    float nq = fmaxf(sqrtf(g_sumsq[b * CQK + h * 8 + i]), 1e-12f);
    float temp = temperature[h];
    float row[8];
    float mx = -1e30f;
#pragma unroll
    for (int j = 0; j < 8; j++) {
        float nk = fmaxf(sqrtf(g_sumsq[b * CQK + 64 + h * 8 + j]), 1e-12f);
        float v = g_gram[((b * 8 + h) * 8 + i) * 8 + j] / (nq * nk) * temp;
        row[j] = v;
        mx = fmaxf(mx, v);
    }
    float s = 0.0f;
#pragma unroll
    for (int j = 0; j < 8; j++) { row[j] = expf(row[j] - mx); s += row[j]; }
    float inv = 1.0f / s;
#pragma unroll
    for (int j = 0; j < 8; j++) attn[((b * 8 + h) * 8 + i) * 8 + j] = row[j] * inv;
    __syncthreads();

    for (int e = tid; e < B * 64 * 64; e += 256) {
        int b2 = e >> 12, oc = (e >> 6) & 63, d = e & 63;
        int h2 = d >> 3, j = d & 7;
        float s2 = 0.0f;
#pragma unroll
        for (int i2 = 0; i2 < 8; i2++)
            s2 += w_proj[oc * 64 + h2 * 8 + i2] * attn[((b2 * 8 + h2) * 8 + i2) * 8 + j];
        g_M[e] = s2;
    }
}

// ---------------- K3: tf32 conv5x5 + gate + epilogue ---------------------------
#define YSTRIDE 408
#define WSTRIDE 72
#define VSTRIDE 68
#define K3_WOFF (32 * YSTRIDE)
#define K3_MOFF (K3_WOFF + 3 * 32 * WSTRIDE)

__global__ __launch_bounds__(256, 2)
void k_conv5_out(const float* __restrict__ x,
                 const float* __restrict__ b_proj,
                 float* __restrict__ out) {
    extern __shared__ float sm[];
    float* ysm = sm;
    float* wsm = sm + K3_WOFF;
    float* Msm = sm + K3_MOFF;

    const int b = blockIdx.z;
    const int tx0 = blockIdx.x * 16, ty0 = blockIdx.y * 16;
    const int tid = threadIdx.x;
    const int w = tid >> 5, lane = tid & 31;
    const int g = lane >> 2, t4 = lane & 3;

    for (int i = tid; i < 4096; i += 256) {
        int ch = i & 63, oc = i >> 6;
        Msm[ch * WSTRIDE + oc] = to_tf32(g_M[b * 4096 + i]);
    }

    float acc[2][8][4];
#pragma unroll
    for (int m = 0; m < 2; m++)
#pragma unroll
        for (int n = 0; n < 8; n++)
#pragma unroll
            for (int j = 0; j < 4; j++) acc[m][n][j] = 0.0f;

    const uint32_t* ysmu = (const uint32_t*)ysm;

    for (int icc = 0; icc < 2; icc++) {
        if (icc) __syncthreads();
        for (int i = tid; i < 32 * 400; i += 256) {
            int ic = i / 400;
            int rem = i - ic * 400;
            int r = rem / 20, cc = rem - r * 20;
            int gy = ty0 - 2 + r, gx = tx0 - 2 + cc;
            float v = 0.0f;
            if (gy >= 0 && gy < HDIM && gx >= 0 && gx < WDIM)
                v = g_y[(size_t)(b * 64 + icc * 32 + ic) * HW + gy * WDIM + gx];
            ysm[ic * YSTRIDE + r * 20 + cc] = v;
        }
        {
            uint32_t base = (uint32_t)__cvta_generic_to_shared(wsm);
            const float* src = g_Wt + icc * 2048;
            for (int i = tid * 4; i < 2048; i += 1024) {
                int k = i >> 6, oc = i & 63;
                cp_async16(base + (uint32_t)(k * WSTRIDE + oc) * 4u, src + i);
            }
            asm volatile("cp.async.commit_group;");
        }

        for (int t = 0; t < 25; t++) {
            const float* wbuf = wsm + (t % 3) * (32 * WSTRIDE);
            if (t + 1 < 25) {
                float* nbuf = wsm + ((t + 1) % 3) * (32 * WSTRIDE);
                uint32_t base = (uint32_t)__cvta_generic_to_shared(nbuf);
                const float* src = g_Wt + (t + 1) * 4096 + icc * 2048;
                for (int i = tid * 4; i < 2048; i += 1024) {
                    int k = i >> 6, oc = i & 63;
                    cp_async16(base + (uint32_t)(k * WSTRIDE + oc) * 4u, src + i);
                }
                asm volatile("cp.async.commit_group;");
                asm volatile("cp.async.wait_group 1;");
            } else {
                asm volatile("cp.async.wait_group 0;");
            }
            __syncthreads();

            const int dy = t / 5, dx = t - dy * 5;
            const uint32_t* wbu = (const uint32_t*)wbuf;
            const int ro0 = (2 * w + dy) * 20 + dx + g;

#pragma unroll
            for (int ks = 0; ks < 4; ks++) {
                int ic = ks * 8 + t4;
                int abase = ic * YSTRIDE + ro0;
                uint32_t a0[4], a1[4];
                a0[0] = ysmu[abase];
                a0[1] = ysmu[abase + 8];
                a0[2] = ysmu[abase + 4 * YSTRIDE];
                a0[3] = ysmu[abase + 4 * YSTRIDE + 8];
                a1[0] = ysmu[abase + 20];
                a1[1] = ysmu[abase + 28];
                a1[2] = ysmu[abase + 4 * YSTRIDE + 20];
                a1[3] = ysmu[abase + 4 * YSTRIDE + 28];
                int bbase = ic * WSTRIDE + g;
#pragma unroll
                for (int n = 0; n < 8; n++) {
                    uint32_t bb[2];
                    bb[0] = wbu[bbase + n * 8];
                    bb[1] = wbu[bbase + 4 * WSTRIDE + n * 8];
                    mma_tf32(acc[0][n], a0, bb);
                    mma_tf32(acc[1][n], a1, bb);
                }
            }
        }
    }
    __syncthreads();

    float* vvsm = sm;
#pragma unroll
    for (int m = 0; m < 2; m++) {
        int py = 2 * w + m;
        int gy = ty0 + py;
#pragma unroll
        for (int n = 0; n < 8; n++) {
#pragma unroll
            for (int j = 0; j < 4; j++) {
                int px = g + ((j >> 1) << 3);
                int ch = n * 8 + t4 * 2 + (j & 1);
                float xv = x[(size_t)(b * 64 + ch) * HW + gy * WDIM + tx0 + px];
                float a = acc[m][n][j];
                float sg = 1.0f / (1.0f + __expf(-a));
                vvsm[(py * 16 + px) * VSTRIDE + ch] = to_tf32(xv * (1.0f + sg));
                acc[m][n][j] = 0.0f;
            }
        }
    }
    __syncthreads();

    const uint32_t* vvu = (const uint32_t*)vvsm;
    const uint32_t* Msu = (const uint32_t*)Msm;
    const int p0 = 32 * w + g;
#pragma unroll
    for (int ks = 0; ks < 8; ks++) {
        int ch = ks * 8 + t4;
        uint32_t a0[4], a1[4];
        a0[0] = vvu[p0 * VSTRIDE + ch];
        a0[1] = vvu[(p0 + 8) * VSTRIDE + ch];
        a0[2] = vvu[p0 * VSTRIDE + ch + 4];
        a0[3] = vvu[(p0 + 8) * VSTRIDE + ch + 4];
        a1[0] = vvu[(p0 + 16) * VSTRIDE + ch];
        a1[1] = vvu[(p0 + 24) * VSTRIDE + ch];
        a1[2] = vvu[(p0 + 16) * VSTRIDE + ch + 4];
        a1[3] = vvu[(p0 + 24) * VSTRIDE + ch + 4];
        int bbase = ch * WSTRIDE + g;
#pragma unroll
        for (int n = 0; n < 8; n++) {
            uint32_t bb[2];
            bb[0] = Msu[bbase + n * 8];
            bb[1] = Msu[bbase + 4 * WSTRIDE + n * 8];
            mma_tf32(acc[0][n], a0, bb);
            mma_tf32(acc[1][n], a1, bb);
        }
    }

#pragma unroll
    for (int m = 0; m < 2; m++) {
        int gy = ty0 + 2 * w + m;
#pragma unroll
        for (int n = 0; n < 8; n++) {
#pragma unroll
            for (int j = 0; j < 4; j++) {
                int px = g + ((j >> 1) << 3);
                int oc = n * 8 + t4 * 2 + (j & 1);
                out[(size_t)(b * 64 + oc) * HW + gy * WDIM + tx0 + px] =
                    acc[m][n][j] + __ldg(&b_proj[oc]);
            }
        }
    }
}

// ---------------- launch ------------------------------------------------------
extern "C" void kernel_launch(void* const* d_in, const int* in_sizes, int n_in,
                              void* d_out, int out_size) {
    const float* x      = (const float*)d_in[0];
    const float* w_qkv  = (const float*)d_in[1];
    const float* b_qkv  = (const float*)d_in[2];
    const float* w_dw   = (const float*)d_in[3];
    const float* b_dw   = (const float*)d_in[4];
    const float* w_proj = (const float*)d_in[5];
    const float* b_proj = (const float*)d_in[6];
    const float* temp   = (const float*)d_in[7];
    const float* w_m1   = (const float*)d_in[8];
    const float* bn_g   = (const float*)d_in[9];
    const float* bn_b   = (const float*)d_in[10];
    const float* bn_m   = (const float*)d_in[11];
    const float* bn_v   = (const float*)d_in[12];
    const float* w_m2   = (const float*)d_in[13];
    float* out = (float*)d_out;

    size_t smem_k0 = (size_t)(64 * PSTR + 64 * OSTR + 384) * sizeof(float);
    size_t smem_dg = (size_t)TOT_U * sizeof(uint32_t);
    size_t smem_k3 = (size_t)(K3_MOFF + 64 * WSTRIDE) * sizeof(float);
    cudaFuncSetAttribute(k_pointwise, cudaFuncAttributeMaxDynamicSharedMemorySize,
                         (int)smem_k0);
    cudaFuncSetAttribute(k_dwgram, cudaFuncAttributeMaxDynamicSharedMemorySize,
                         (int)smem_dg);
    cudaFuncSetAttribute(k_conv5_out, cudaFuncAttributeMaxDynamicSharedMemorySize,
                         (int)smem_k3);

    k_zero<<<8, 256>>>();
    k_wt<<<400, 256>>>(w_m2);
    k_pointwise<<<dim3(HW / 128, B), 256, smem_k0>>>(x, w_qkv, b_qkv, w_m1,
                                                     bn_g, bn_b, bn_m, bn_v);
    k_dwgram<<<dim3(8, 8, B * HEADS), 256, smem_dg>>>(w_dw, b_dw);
    k_attn<<<1, 256>>>(w_proj, temp);
    k_conv5_out<<<dim3(16, 16, B), 256, smem_k3>>>(x, b_proj, out);
}